// round 3
// baseline (speedup 1.0000x reference)
#include <cuda_runtime.h>
#include <cstdint>

// ============================================================================
// Quantized linear layer (distiller RangeLinearQuantParamLayerWrapper)
//   x[4096,4096] f32, W[4096,4096] f32 ([out,in]), b[4096] f32 -> out[4096,4096] f32
//
// NOTE: harness compiles for target sm_100 (base, NOT sm_100a) -> no tcgen05/TMEM.
// Use baseline-PTX path: int8 mma.sync (m16n8k32 s8*s8+s32) + cp.async pipeline.
// int8 MMA with s32 accumulation is EXACT integer math == reference semantics.
// ============================================================================

#define DIM 4096
#define NELEM (DIM * DIM)

// ---------------- scratch (device globals; no runtime allocation) -----------
__device__ __align__(16) signed char g_xq8[NELEM];   // 16 MB
__device__ __align__(16) signed char g_wq8[NELEM];   // 16 MB
__device__ float         g_accum[NELEM];             // 64 MB
__device__ float         g_bq[DIM];
__device__ unsigned      g_umax[4];                  // max|x|,max|W|,max|b|,max|accum| (uint bits)
__device__ float         g_scales[8];                // 0:in_s 1:w_s 2:b_s 3:acc_s 4:acc_s/b_s 5:out_s 6:out_s/acc_s

// ============================================================================
// small kernels
// ============================================================================
__global__ void k_init() {
    if (threadIdx.x < 4) g_umax[threadIdx.x] = 0u;
}

__global__ void k_maxabs(const float4* __restrict__ p, int n4, int slot) {
    float m = 0.f;
    for (int i = blockIdx.x * blockDim.x + threadIdx.x; i < n4; i += gridDim.x * blockDim.x) {
        float4 v = p[i];
        m = fmaxf(m, fmaxf(fmaxf(fabsf(v.x), fabsf(v.y)), fmaxf(fabsf(v.z), fabsf(v.w))));
    }
    #pragma unroll
    for (int o = 16; o; o >>= 1) m = fmaxf(m, __shfl_xor_sync(0xFFFFFFFFu, m, o));
    __shared__ float sm[32];
    int w = threadIdx.x >> 5, l = threadIdx.x & 31;
    if (l == 0) sm[w] = m;
    __syncthreads();
    if (w == 0) {
        m = (l < (int)(blockDim.x >> 5)) ? sm[l] : 0.f;
        #pragma unroll
        for (int o = 16; o; o >>= 1) m = fmaxf(m, __shfl_xor_sync(0xFFFFFFFFu, m, o));
        if (l == 0) atomicMax(&g_umax[slot], __float_as_uint(m));
    }
}

__global__ void k_scales1() {
    float mx = __uint_as_float(g_umax[0]);
    float mw = __uint_as_float(g_umax[1]);
    float mb = __uint_as_float(g_umax[2]);
    float in_s  = 255.0f / (2.0f * mx);
    float w_s   = 255.0f / (2.0f * mw);
    float b_s   = 255.0f / (2.0f * mb);
    float acc_s = in_s * w_s;
    g_scales[0] = in_s; g_scales[1] = w_s; g_scales[2] = b_s;
    g_scales[3] = acc_s; g_scales[4] = acc_s / b_s;
}

__global__ void k_bq(const float* __restrict__ b) {
    int i = blockIdx.x * blockDim.x + threadIdx.x;
    if (i < DIM) {
        float bs = g_scales[2], rb = g_scales[4];
        float base = fminf(127.f, fmaxf(-128.f, rintf(b[i] * bs)));
        g_bq[i] = rintf(base * rb);  // |val| << 2^31 -> accum-range clip is a no-op
    }
}

// quantize f32 -> s8 (16 floats -> 16 bytes per thread iteration)
__global__ void k_quant8(const float4* __restrict__ src, int which) {
    float s = which ? g_scales[1] : g_scales[0];
    int4* dst = reinterpret_cast<int4*>(which ? g_wq8 : g_xq8);
    int n16 = NELEM / 16;
    for (int i = blockIdx.x * blockDim.x + threadIdx.x; i < n16; i += gridDim.x * blockDim.x) {
        int p[4];
        #pragma unroll
        for (int j = 0; j < 4; j++) {
            float4 v = src[i * 4 + j];
            int q0 = max(-128, min(127, __float2int_rn(v.x * s)));
            int q1 = max(-128, min(127, __float2int_rn(v.y * s)));
            int q2 = max(-128, min(127, __float2int_rn(v.z * s)));
            int q3 = max(-128, min(127, __float2int_rn(v.w * s)));
            p[j] = (q0 & 0xFF) | ((q1 & 0xFF) << 8) | ((q2 & 0xFF) << 16) | ((q3 & 0xFF) << 24);
        }
        dst[i] = make_int4(p[0], p[1], p[2], p[3]);
    }
}

__global__ void k_scales2() {
    float macc  = __uint_as_float(g_umax[3]);
    float acc_s = g_scales[3];
    float out_sat = macc / acc_s;
    float out_s = 255.0f / (2.0f * out_sat);
    g_scales[5] = out_s;
    g_scales[6] = out_s / acc_s;
}

__global__ void k_requant(float4* __restrict__ out, int n4) {
    float ratio = g_scales[6], os = g_scales[5];
    const float4* acc = reinterpret_cast<const float4*>(g_accum);
    for (int i = blockIdx.x * blockDim.x + threadIdx.x; i < n4; i += gridDim.x * blockDim.x) {
        float4 v = acc[i];
        float4 o;
        o.x = fminf(127.f, fmaxf(-128.f, rintf(v.x * ratio))) / os;
        o.y = fminf(127.f, fmaxf(-128.f, rintf(v.y * ratio))) / os;
        o.z = fminf(127.f, fmaxf(-128.f, rintf(v.z * ratio))) / os;
        o.w = fminf(127.f, fmaxf(-128.f, rintf(v.w * ratio))) / os;
        out[i] = o;
    }
}

// ============================================================================
// int8 GEMM: accum[m,n] = sum_k xq[m,k]*wq[n,k] + bq[n]; plus global max|accum|
//   block 128x128, BK=64, 8 warps (warp tile 64x32), 3-stage cp.async pipeline
//   mma.sync.aligned.m16n8k32.row.col.s32.s8.s8.s32
// ============================================================================
#define BM 128
#define BN 128
#define BK 64
#define NSTAGE 3
#define KSTAGES (DIM / BK)     // 64
#define ROWPAD 80              // 64-byte rows padded to 80 B: conflict-free 4B frag loads
#define STAGE_BYTES (128 * ROWPAD)             // 10240 per operand per stage
#define GEMM_SMEM_BYTES (NSTAGE * 2 * STAGE_BYTES)  // 61440

__device__ __forceinline__ uint32_t smem_u32(const void* p) {
    uint32_t a;
    asm("{ .reg .u64 t; cvta.to.shared.u64 t, %1; cvt.u32.u64 %0, t; }" : "=r"(a) : "l"(p));
    return a;
}

__device__ __forceinline__ void cpasync16(uint32_t dst, const void* src) {
    asm volatile("cp.async.cg.shared.global [%0], [%1], 16;" :: "r"(dst), "l"(src) : "memory");
}
#define CP_COMMIT() asm volatile("cp.async.commit_group;" ::: "memory")
#define CP_WAIT1()  asm volatile("cp.async.wait_group 1;" ::: "memory")

__device__ __forceinline__ void mma_s8(int* d, const unsigned* a, const unsigned* b) {
    asm volatile(
        "mma.sync.aligned.m16n8k32.row.col.s32.s8.s8.s32 "
        "{%0,%1,%2,%3}, {%4,%5,%6,%7}, {%8,%9}, {%0,%1,%2,%3};"
        : "+r"(d[0]), "+r"(d[1]), "+r"(d[2]), "+r"(d[3])
        : "r"(a[0]), "r"(a[1]), "r"(a[2]), "r"(a[3]), "r"(b[0]), "r"(b[1]));
}

__device__ __forceinline__ void load_stage(uint32_t sA, uint32_t sB, int s,
                                           const signed char* Ag, const signed char* Bg,
                                           int tid) {
    int k0 = s * BK;
    #pragma unroll
    for (int i = 0; i < 2; i++) {
        int chunk = tid + i * 256;          // 0..511
        int r = chunk >> 2, c = chunk & 3;  // row 0..127, 16B chunk 0..3
        uint32_t soff = (uint32_t)(r * ROWPAD + c * 16);
        cpasync16(sA + soff, Ag + (size_t)r * DIM + k0 + c * 16);
        cpasync16(sB + soff, Bg + (size_t)r * DIM + k0 + c * 16);
    }
    CP_COMMIT();
}

__global__ void __launch_bounds__(256, 2) k_gemm() {
    extern __shared__ char dsm[];
    __shared__ float s_bq[BN];

    const int tid  = threadIdx.x;
    const int wid  = tid >> 5;
    const int lane = tid & 31;
    const int m0 = blockIdx.y * BM;
    const int n0 = blockIdx.x * BN;
    const int warp_m = (wid >> 2) * 64;   // 0 or 64
    const int warp_n = (wid & 3) * 32;    // 0,32,64,96

    uint32_t sA0 = smem_u32(dsm);
    uint32_t sB0 = sA0 + NSTAGE * STAGE_BYTES;

    if (tid < BN) s_bq[tid] = g_bq[n0 + tid];

    const signed char* Ag = g_xq8 + (size_t)m0 * DIM;
    const signed char* Bg = g_wq8 + (size_t)n0 * DIM;

    int acc[4][4][4];  // [im][in][4]
    #pragma unroll
    for (int im = 0; im < 4; im++)
        #pragma unroll
        for (int in = 0; in < 4; in++)
            #pragma unroll
            for (int j = 0; j < 4; j++) acc[im][in][j] = 0;

    load_stage(sA0, sB0, 0, Ag, Bg, tid);
    load_stage(sA0 + STAGE_BYTES, sB0 + STAGE_BYTES, 1, Ag, Bg, tid);

    const int r = lane >> 2;     // 0..7
    const int c = lane & 3;      // 0..3

    for (int s = 0; s < KSTAGES; s++) {
        int buf = s % NSTAGE;
        CP_WAIT1();
        __syncthreads();

        // prefetch stage s+2 into buffer (s+2)%NSTAGE (last read in iter s-1)
        if (s + 2 < KSTAGES) {
            int nb = (s + 2) % NSTAGE;
            load_stage(sA0 + nb * STAGE_BYTES, sB0 + nb * STAGE_BYTES, s + 2, Ag, Bg, tid);
        } else {
            CP_COMMIT();
        }

        const unsigned* A32 = reinterpret_cast<const unsigned*>(dsm + buf * STAGE_BYTES);
        const unsigned* B32 = reinterpret_cast<const unsigned*>(dsm + NSTAGE * STAGE_BYTES + buf * STAGE_BYTES);

        #pragma unroll
        for (int kstep = 0; kstep < 2; kstep++) {
            int kq = kstep * 8 + c;  // u32 index within padded row (k bytes = kstep*32 + c*4)
            unsigned afrag[4][4];
            #pragma unroll
            for (int im = 0; im < 4; im++) {
                int row = warp_m + im * 16 + r;
                int base = row * (ROWPAD / 4) + kq;
                afrag[im][0] = A32[base];
                afrag[im][1] = A32[base + 8 * (ROWPAD / 4)];
                afrag[im][2] = A32[base + 4];
                afrag[im][3] = A32[base + 8 * (ROWPAD / 4) + 4];
            }
            unsigned bfrag[4][2];
            #pragma unroll
            for (int in = 0; in < 4; in++) {
                int n = warp_n + in * 8 + r;
                int base = n * (ROWPAD / 4) + kq;
                bfrag[in][0] = B32[base];
                bfrag[in][1] = B32[base + 4];
            }
            #pragma unroll
            for (int im = 0; im < 4; im++)
                #pragma unroll
                for (int in = 0; in < 4; in++)
                    mma_s8(acc[im][in], afrag[im], bfrag[in]);
        }
    }

    // -------- epilogue: + bq, write f32 accum, global max|accum| --------
    __syncthreads();  // s_bq visibility (also separates last compute)
    float lmax = 0.f;
    #pragma unroll
    for (int im = 0; im < 4; im++) {
        int r0 = m0 + warp_m + im * 16 + r;
        #pragma unroll
        for (int in = 0; in < 4; in++) {
            int cl = warp_n + in * 8 + c * 2;   // col within tile
            float b0 = s_bq[cl], b1 = s_bq[cl + 1];
            float v0 = (float)acc[im][in][0] + b0;
            float v1 = (float)acc[im][in][1] + b1;
            float v2 = (float)acc[im][in][2] + b0;
            float v3 = (float)acc[im][in][3] + b1;
            lmax = fmaxf(lmax, fmaxf(fmaxf(fabsf(v0), fabsf(v1)), fmaxf(fabsf(v2), fabsf(v3))));
            float2* p0 = reinterpret_cast<float2*>(g_accum + (size_t)r0 * DIM + n0 + cl);
            float2* p1 = reinterpret_cast<float2*>(g_accum + (size_t)(r0 + 8) * DIM + n0 + cl);
            *p0 = make_float2(v0, v1);
            *p1 = make_float2(v2, v3);
        }
    }
    #pragma unroll
    for (int o = 16; o; o >>= 1) lmax = fmaxf(lmax, __shfl_xor_sync(0xFFFFFFFFu, lmax, o));
    if (lane == 0) atomicMax(&g_umax[3], __float_as_uint(lmax));
}

// ============================================================================
// kernel_launch
// ============================================================================
extern "C" void kernel_launch(void* const* d_in, const int* in_sizes, int n_in,
                              void* d_out, int out_size) {
    const float* x = (const float*)d_in[0];
    const float* W = (const float*)d_in[1];
    const float* b = (const float*)d_in[2];

    cudaFuncSetAttribute(k_gemm, cudaFuncAttributeMaxDynamicSharedMemorySize, GEMM_SMEM_BYTES);

    k_init<<<1, 32>>>();
    k_maxabs<<<1024, 256>>>((const float4*)x, NELEM / 4, 0);
    k_maxabs<<<1024, 256>>>((const float4*)W, NELEM / 4, 1);
    k_maxabs<<<4, 256>>>((const float4*)b, DIM / 4, 2);
    k_scales1<<<1, 1>>>();
    k_bq<<<DIM / 256, 256>>>(b);
    k_quant8<<<2048, 256>>>((const float4*)x, 0);
    k_quant8<<<2048, 256>>>((const float4*)W, 1);

    dim3 grid(DIM / BN, DIM / BM);
    k_gemm<<<grid, 256, GEMM_SMEM_BYTES>>>();

    k_scales2<<<1, 1>>>();
    k_requant<<<2048, 256>>>((float4*)d_out, NELEM / 4);
}

// round 5
// speedup vs baseline: 1.1271x; 1.1271x over previous
#include <cuda_runtime.h>
#include <cstdint>

// ============================================================================
// Quantized linear layer (distiller RangeLinearQuantParamLayerWrapper)
//   x[4096,4096] f32, W[4096,4096] f32 ([out,in]), b[4096] f32 -> out[4096,4096] f32
//
// Target is base sm_100 (no tcgen05/TMEM). int8 mma.sync m16n8k32 s8*s8+s32
// (exact integer math == reference semantics) + cp.async 4-stage pipeline
// + ldmatrix.x4 fragment loads.
// ============================================================================

#define DIM 4096
#define NELEM (DIM * DIM)

// ---------------- scratch (device globals; no runtime allocation) -----------
__device__ __align__(16) signed char g_xq8[NELEM];   // 16 MB
__device__ __align__(16) signed char g_wq8[NELEM];   // 16 MB
__device__ float         g_accum[NELEM];             // 64 MB
__device__ float         g_bq[DIM];
__device__ unsigned      g_umax[4];                  // max|x|,max|W|,max|b|,max|accum| (uint bits)

// ============================================================================
// small kernels (scales recomputed inline from g_umax -> fewer launches)
// ============================================================================
__global__ void k_init() {
    if (threadIdx.x < 4) g_umax[threadIdx.x] = 0u;
}

__device__ __forceinline__ void maxabs_body(const float4* __restrict__ p, int n4,
                                            int slot, int bi, int nblk) {
    float m = 0.f;
    for (int i = bi * blockDim.x + threadIdx.x; i < n4; i += nblk * blockDim.x) {
        float4 v = p[i];
        m = fmaxf(m, fmaxf(fmaxf(fabsf(v.x), fabsf(v.y)), fmaxf(fabsf(v.z), fabsf(v.w))));
    }
    #pragma unroll
    for (int o = 16; o; o >>= 1) m = fmaxf(m, __shfl_xor_sync(0xFFFFFFFFu, m, o));
    __shared__ float sm[32];
    int w = threadIdx.x >> 5, l = threadIdx.x & 31;
    if (l == 0) sm[w] = m;
    __syncthreads();
    if (w == 0) {
        m = (l < (int)(blockDim.x >> 5)) ? sm[l] : 0.f;
        #pragma unroll
        for (int o = 16; o; o >>= 1) m = fmaxf(m, __shfl_xor_sync(0xFFFFFFFFu, m, o));
        if (l == 0) atomicMax(&g_umax[slot], __float_as_uint(m));
    }
}

// one launch: first half of blocks reduce x, second half reduce W
__global__ void k_maxabs2(const float4* __restrict__ x, const float4* __restrict__ W) {
    int nb = gridDim.x >> 1;
    if ((int)blockIdx.x < nb) maxabs_body(x, NELEM / 4, 0, blockIdx.x, nb);
    else                      maxabs_body(W, NELEM / 4, 1, blockIdx.x - nb, nb);
}

__global__ void k_maxabs1(const float4* __restrict__ p, int n4, int slot) {
    maxabs_body(p, n4, slot, blockIdx.x, gridDim.x);
}

__global__ void k_bq(const float* __restrict__ b) {
    int i = blockIdx.x * blockDim.x + threadIdx.x;
    if (i < DIM) {
        float in_s = 255.0f / (2.0f * __uint_as_float(g_umax[0]));
        float w_s  = 255.0f / (2.0f * __uint_as_float(g_umax[1]));
        float b_s  = 255.0f / (2.0f * __uint_as_float(g_umax[2]));
        float rb   = (in_s * w_s) / b_s;
        float base = fminf(127.f, fmaxf(-128.f, rintf(b[i] * b_s)));
        g_bq[i] = rintf(base * rb);  // |val| << 2^31 -> accum-range clip is a no-op
    }
}

// quantize both x and W -> s8 in one launch (16 floats -> 16 bytes per iter)
__global__ void k_quant8(const float4* __restrict__ x, const float4* __restrict__ W) {
    float sx = 255.0f / (2.0f * __uint_as_float(g_umax[0]));
    float sw = 255.0f / (2.0f * __uint_as_float(g_umax[1]));
    const int n16 = NELEM / 16;
    for (int i = blockIdx.x * blockDim.x + threadIdx.x; i < 2 * n16; i += gridDim.x * blockDim.x) {
        int which = i >= n16;
        int idx = which ? i - n16 : i;
        const float4* src = which ? W : x;
        float s = which ? sw : sx;
        int4* dst = reinterpret_cast<int4*>(which ? g_wq8 : g_xq8);
        int p[4];
        #pragma unroll
        for (int j = 0; j < 4; j++) {
            float4 v = src[idx * 4 + j];
            int q0 = max(-128, min(127, __float2int_rn(v.x * s)));
            int q1 = max(-128, min(127, __float2int_rn(v.y * s)));
            int q2 = max(-128, min(127, __float2int_rn(v.z * s)));
            int q3 = max(-128, min(127, __float2int_rn(v.w * s)));
            p[j] = (q0 & 0xFF) | ((q1 & 0xFF) << 8) | ((q2 & 0xFF) << 16) | ((q3 & 0xFF) << 24);
        }
        dst[idx] = make_int4(p[0], p[1], p[2], p[3]);
    }
}

__global__ void k_requant(float4* __restrict__ out, int n4) {
    float in_s   = 255.0f / (2.0f * __uint_as_float(g_umax[0]));
    float w_s    = 255.0f / (2.0f * __uint_as_float(g_umax[1]));
    float acc_s  = in_s * w_s;
    float out_sat = __uint_as_float(g_umax[3]) / acc_s;
    float out_s  = 255.0f / (2.0f * out_sat);
    float ratio  = out_s / acc_s;
    const float4* acc = reinterpret_cast<const float4*>(g_accum);
    for (int i = blockIdx.x * blockDim.x + threadIdx.x; i < n4; i += gridDim.x * blockDim.x) {
        float4 v = acc[i];
        float4 o;
        o.x = fminf(127.f, fmaxf(-128.f, rintf(v.x * ratio))) / out_s;
        o.y = fminf(127.f, fmaxf(-128.f, rintf(v.y * ratio))) / out_s;
        o.z = fminf(127.f, fmaxf(-128.f, rintf(v.z * ratio))) / out_s;
        o.w = fminf(127.f, fmaxf(-128.f, rintf(v.w * ratio))) / out_s;
        out[i] = o;
    }
}

// ============================================================================
// int8 GEMM: accum[m,n] = sum_k xq[m,k]*wq[n,k] + bq[n]; plus global max|accum|
//   block 128x128, BK=64, 8 warps (warp tile 64x32), 4-stage cp.async pipeline
//   ldmatrix.x4 fragment loads, mma.sync.m16n8k32.s8.s8.s32
// ============================================================================
#define BM 128
#define BN 128
#define BK 64
#define NSTAGE 4
#define KSTAGES (DIM / BK)     // 64
#define ROWPAD 80              // 64B rows padded to 80B: 8-row ldmatrix banks distinct
#define STAGE_BYTES (128 * ROWPAD)                    // 10240 per operand per stage
#define GEMM_SMEM_BYTES (NSTAGE * 2 * STAGE_BYTES)    // 81920

__device__ __forceinline__ uint32_t smem_u32(const void* p) {
    uint32_t a;
    asm("{ .reg .u64 t; cvta.to.shared.u64 t, %1; cvt.u32.u64 %0, t; }" : "=r"(a) : "l"(p));
    return a;
}

__device__ __forceinline__ void cpasync16(uint32_t dst, const void* src) {
    asm volatile("cp.async.cg.shared.global [%0], [%1], 16;" :: "r"(dst), "l"(src) : "memory");
}
#define CP_COMMIT() asm volatile("cp.async.commit_group;" ::: "memory")
#define CP_WAIT2()  asm volatile("cp.async.wait_group 2;" ::: "memory")

__device__ __forceinline__ void ldsm4(unsigned& r0, unsigned& r1, unsigned& r2, unsigned& r3,
                                      uint32_t addr) {
    asm volatile("ldmatrix.sync.aligned.m8n8.x4.shared.b16 {%0,%1,%2,%3}, [%4];"
                 : "=r"(r0), "=r"(r1), "=r"(r2), "=r"(r3) : "r"(addr));
}

__device__ __forceinline__ void mma_s8(int* d, const unsigned* a, const unsigned* b) {
    asm volatile(
        "mma.sync.aligned.m16n8k32.row.col.s32.s8.s8.s32 "
        "{%0,%1,%2,%3}, {%4,%5,%6,%7}, {%8,%9}, {%0,%1,%2,%3};"
        : "+r"(d[0]), "+r"(d[1]), "+r"(d[2]), "+r"(d[3])
        : "r"(a[0]), "r"(a[1]), "r"(a[2]), "r"(a[3]), "r"(b[0]), "r"(b[1]));
}

__device__ __forceinline__ void load_stage(uint32_t sA, uint32_t sB, int s,
                                           const signed char* Ag, const signed char* Bg,
                                           int tid) {
    int k0 = s * BK;
    #pragma unroll
    for (int i = 0; i < 2; i++) {
        int chunk = tid + i * 256;          // 0..511
        int r = chunk >> 2, c = chunk & 3;  // row 0..127, 16B chunk 0..3
        uint32_t soff = (uint32_t)(r * ROWPAD + c * 16);
        cpasync16(sA + soff, Ag + (size_t)r * DIM + k0 + c * 16);
        cpasync16(sB + soff, Bg + (size_t)r * DIM + k0 + c * 16);
    }
    CP_COMMIT();
}

__global__ void __launch_bounds__(256, 2) k_gemm() {
    extern __shared__ char dsm[];
    __shared__ float s_bq[BN];

    const int tid  = threadIdx.x;
    const int wid  = tid >> 5;
    const int lane = tid & 31;
    const int m0 = blockIdx.y * BM;
    const int n0 = blockIdx.x * BN;
    const int warp_m = (wid >> 2) * 64;   // 0 or 64
    const int warp_n = (wid & 3) * 32;    // 0,32,64,96

    uint32_t sA0 = smem_u32(dsm);
    uint32_t sB0 = sA0 + NSTAGE * STAGE_BYTES;

    if (tid < BN) s_bq[tid] = g_bq[n0 + tid];

    const signed char* Ag = g_xq8 + (size_t)m0 * DIM;
    const signed char* Bg = g_wq8 + (size_t)n0 * DIM;

    int acc[4][4][4];
    #pragma unroll
    for (int im = 0; im < 4; im++)
        #pragma unroll
        for (int in = 0; in < 4; in++)
            #pragma unroll
            for (int j = 0; j < 4; j++) acc[im][in][j] = 0;

    load_stage(sA0, sB0, 0, Ag, Bg, tid);
    load_stage(sA0 + STAGE_BYTES, sB0 + STAGE_BYTES, 1, Ag, Bg, tid);
    load_stage(sA0 + 2 * STAGE_BYTES, sB0 + 2 * STAGE_BYTES, 2, Ag, Bg, tid);

    // ldmatrix per-thread address components
    //  A (16x32 tile at row base): t0-15 -> row base+(t&15), k+0 ; t16-31 -> row base+(t&15), k+16
    const uint32_t a_off = (uint32_t)((lane & 15) * ROWPAD + ((lane >> 4) << 4));
    //  B (two 8-row n-tiles): row = nbase + (t&7) + ((t>=16)?8:0) ; k = ((t>>3)&1)*16
    const uint32_t b_off = (uint32_t)((((lane & 7) + ((lane >> 4) << 3)) * ROWPAD) + (((lane >> 3) & 1) << 4));

    for (int s = 0; s < KSTAGES; s++) {
        int buf = s % NSTAGE;
        CP_WAIT2();
        __syncthreads();

        // prefetch stage s+3 into buffer (s+3)%NSTAGE (its old data was consumed at iter s-1)
        if (s + 3 < KSTAGES) {
            int nb = (s + 3) % NSTAGE;
            load_stage(sA0 + nb * STAGE_BYTES, sB0 + nb * STAGE_BYTES, s + 3, Ag, Bg, tid);
        } else {
            CP_COMMIT();
        }

        uint32_t aBase = sA0 + buf * STAGE_BYTES + (uint32_t)(warp_m * ROWPAD) + a_off;
        uint32_t bBase = sB0 + buf * STAGE_BYTES + (uint32_t)(warp_n * ROWPAD) + b_off;

        #pragma unroll
        for (int kstep = 0; kstep < 2; kstep++) {
            uint32_t kb = (uint32_t)(kstep * 32);
            unsigned afrag[4][4];
            #pragma unroll
            for (int im = 0; im < 4; im++)
                ldsm4(afrag[im][0], afrag[im][1], afrag[im][2], afrag[im][3],
                      aBase + (uint32_t)(im * 16 * ROWPAD) + kb);
            unsigned bfrag[4][2];
            #pragma unroll
            for (int p = 0; p < 2; p++)
                ldsm4(bfrag[2 * p][0], bfrag[2 * p][1], bfrag[2 * p + 1][0], bfrag[2 * p + 1][1],
                      bBase + (uint32_t)(p * 16 * ROWPAD) + kb);
            #pragma unroll
            for (int im = 0; im < 4; im++)
                #pragma unroll
                for (int in = 0; in < 4; in++)
                    mma_s8(acc[im][in], afrag[im], bfrag[in]);
        }
    }

    // -------- epilogue: + bq, write f32 accum, global max|accum| --------
    __syncthreads();
    const int r = lane >> 2;
    const int c = lane & 3;
    float lmax = 0.f;
    #pragma unroll
    for (int im = 0; im < 4; im++) {
        int r0 = m0 + warp_m + im * 16 + r;
        #pragma unroll
        for (int in = 0; in < 4; in++) {
            int cl = warp_n + in * 8 + c * 2;
            float b0 = s_bq[cl], b1 = s_bq[cl + 1];
            float v0 = (float)acc[im][in][0] + b0;
            float v1 = (float)acc[im][in][1] + b1;
            float v2 = (float)acc[im][in][2] + b0;
            float v3 = (float)acc[im][in][3] + b1;
            lmax = fmaxf(lmax, fmaxf(fmaxf(fabsf(v0), fabsf(v1)), fmaxf(fabsf(v2), fabsf(v3))));
            float2* p0 = reinterpret_cast<float2*>(g_accum + (size_t)r0 * DIM + n0 + cl);
            float2* p1 = reinterpret_cast<float2*>(g_accum + (size_t)(r0 + 8) * DIM + n0 + cl);
            *p0 = make_float2(v0, v1);
            *p1 = make_float2(v2, v3);
        }
    }
    #pragma unroll
    for (int o = 16; o; o >>= 1) lmax = fmaxf(lmax, __shfl_xor_sync(0xFFFFFFFFu, lmax, o));
    if (lane == 0) atomicMax(&g_umax[3], __float_as_uint(lmax));
}

// ============================================================================
// kernel_launch
// ============================================================================
extern "C" void kernel_launch(void* const* d_in, const int* in_sizes, int n_in,
                              void* d_out, int out_size) {
    const float* x = (const float*)d_in[0];
    const float* W = (const float*)d_in[1];
    const float* b = (const float*)d_in[2];

    cudaFuncSetAttribute(k_gemm, cudaFuncAttributeMaxDynamicSharedMemorySize, GEMM_SMEM_BYTES);

    k_init<<<1, 32>>>();
    k_maxabs2<<<2048, 256>>>((const float4*)x, (const float4*)W);
    k_maxabs1<<<4, 256>>>((const float4*)b, DIM / 4, 2);
    k_bq<<<DIM / 256, 256>>>(b);
    k_quant8<<<2048, 256>>>((const float4*)x, (const float4*)W);

    dim3 grid(DIM / BN, DIM / BM);
    k_gemm<<<grid, 256, GEMM_SMEM_BYTES>>>();

    k_requant<<<2048, 256>>>((float4*)d_out, NELEM / 4);
}